// round 6
// baseline (speedup 1.0000x reference)
#include <cuda_runtime.h>
#include <cstdint>

// Internal heap nodes, heap-indexed. Only levels 12..20 (heap [4096, 2^21))
// are materialized; levels 21..23 are recomputed in registers from a 64B leaf
// burst; levels 0..11 are rebuilt in smem per descend block. All sums use the
// identical left+right pairing as the reference's reshape(-1,2).sum(axis=1),
// so every comparison is bitwise-exact.
#define BOUND (1 << 24)
__device__ float g_tree[1 << 21];   // only [4096, 2^21) used; 8 MB

// ---------------------------------------------------------------------------
// Build: each block reduces 4096 contiguous leaves; stores only levels 20..12.
// ---------------------------------------------------------------------------
__global__ __launch_bounds__(256) void build_lower(const float* __restrict__ leaf) {
    const int b = blockIdx.x;           // 4096 blocks
    const int t = threadIdx.x;
    const int lane = t & 31;
    const int w = t >> 5;               // 8 warps
    __shared__ float s17[32];

    const float4* __restrict__ in = reinterpret_cast<const float4*>(leaf) + (size_t)b * 1024;

    float* g20 = g_tree + (1u << 20) + (size_t)b * 256;
    float* g19 = g_tree + (1u << 19) + (size_t)b * 128;
    float* g18 = g_tree + (1u << 18) + (size_t)b * 64;
    float* g17 = g_tree + (1u << 17) + (size_t)b * 32;

#pragma unroll
    for (int r = 0; r < 4; ++r) {
        const int q = r * 256 + t;                    // level-22 node id in block
        float4 a = in[q];                             // coalesced LDG.128
        float v = (a.x + a.y) + (a.z + a.w);          // level-22 value (exact pairing)
        float u;
        u = __shfl_down_sync(0xffffffffu, v, 1);  v += u;   // level 21 (not stored)
        u = __shfl_down_sync(0xffffffffu, v, 2);  v += u;   // level 20
        if (!(lane & 3))  g20[r * 64 + w * 8 + (lane >> 2)] = v;
        u = __shfl_down_sync(0xffffffffu, v, 4);  v += u;   // level 19
        if (!(lane & 7))  g19[r * 32 + w * 4 + (lane >> 3)] = v;
        u = __shfl_down_sync(0xffffffffu, v, 8);  v += u;   // level 18
        if (!(lane & 15)) g18[r * 16 + w * 2 + (lane >> 4)] = v;
        u = __shfl_down_sync(0xffffffffu, v, 16); v += u;   // level 17
        if (lane == 0) { g17[r * 8 + w] = v; s17[r * 8 + w] = v; }
    }
    __syncthreads();

    if (w == 0) {
        float v = s17[lane];
        float u;
        float* g16 = g_tree + (1u << 16) + (size_t)b * 16;
        float* g15 = g_tree + (1u << 15) + (size_t)b * 8;
        float* g14 = g_tree + (1u << 14) + (size_t)b * 4;
        float* g13 = g_tree + (1u << 13) + (size_t)b * 2;
        float* g12 = g_tree + (1u << 12) + (size_t)b;
        u = __shfl_down_sync(0xffffffffu, v, 1);  v += u;
        if (!(lane & 1))  g16[lane >> 1] = v;
        u = __shfl_down_sync(0xffffffffu, v, 2);  v += u;
        if (!(lane & 3))  g15[lane >> 2] = v;
        u = __shfl_down_sync(0xffffffffu, v, 4);  v += u;
        if (!(lane & 7))  g14[lane >> 3] = v;
        u = __shfl_down_sync(0xffffffffu, v, 8);  v += u;
        if (!(lane & 15)) g13[lane >> 4] = v;
        u = __shfl_down_sync(0xffffffffu, v, 16); v += u;
        if (lane == 0)    g12[0] = v;
    }
}

// ---------------------------------------------------------------------------
// Descend: 4 queries per thread (interleaved => 4x MLP at fixed warp count).
// Levels 1..12 in smem; levels 13..20 in rounds of (3,3,2) levels with
// VECTORIZED speculative loads (scalar + float4@4i + 2x float4@8i: same cache
// lines, half the instructions); levels 21..24 + priority from one 64B burst.
// ---------------------------------------------------------------------------
#define QPT 4
__global__ __launch_bounds__(256) void descend(const float* __restrict__ leaf,
                                               const float* __restrict__ frac,
                                               float* __restrict__ out,
                                               int batch) {
    __shared__ float s[8192];
    const int t = threadIdx.x;
    const int qbase = blockIdx.x * 256 * QPT + t;

    float f[QPT];
#pragma unroll
    for (int j = 0; j < QPT; ++j) {
        int q = qbase + j * 256;
        f[j] = (q < batch) ? frac[q] : 0.0f;    // overlap with staging
    }

    // Stage level 12 (heap [4096, 8192)).
    {
        float4* s4p = reinterpret_cast<float4*>(s);
        const float4* g4 = reinterpret_cast<const float4*>(g_tree);
#pragma unroll
        for (int i = t; i < 1024; i += 256) s4p[1024 + i] = g4[1024 + i];
    }
    __syncthreads();
    // Rebuild levels 11..0.
#pragma unroll
    for (int n = 2048; n >= 1; n >>= 1) {
        for (int i = t; i < n; i += 256)
            s[n + i] = s[2 * (n + i)] + s[2 * (n + i) + 1];
        __syncthreads();
    }

    float v[QPT];
    int idx[QPT];
#pragma unroll
    for (int j = 0; j < QPT; ++j) { v[j] = f[j] * s[1]; idx[j] = 1; }

    // Levels 1..12: smem (all queries interleaved).
#pragma unroll
    for (int d = 0; d < 12; ++d) {
        float l[QPT];
#pragma unroll
        for (int j = 0; j < QPT; ++j) { idx[j] <<= 1; l[j] = s[idx[j]]; }
#pragma unroll
        for (int j = 0; j < QPT; ++j) {
            bool r = (l[j] < v[j]);
            v[j] = r ? (v[j] - l[j]) : v[j];
            idx[j] += (int)r;
        }
    }

    // Levels 13..20: two 3-level rounds, then one 2-level round.
#pragma unroll
    for (int round = 0; round < 2; ++round) {
        float a[QPT];
        float4 b[QPT], c0[QPT], c1[QPT];
#pragma unroll
        for (int j = 0; j < QPT; ++j) {
            int i = idx[j];
            a[j]  = __ldg(&g_tree[2 * i]);
            b[j]  = __ldg(reinterpret_cast<const float4*>(&g_tree[4 * i]));      // 16B aligned
            c0[j] = __ldg(reinterpret_cast<const float4*>(&g_tree[8 * i]));      // 32B aligned
            c1[j] = __ldg(reinterpret_cast<const float4*>(&g_tree[8 * i + 4]));
        }
#pragma unroll
        for (int j = 0; j < QPT; ++j) {
            bool r1 = (a[j] < v[j]);  v[j] = r1 ? (v[j] - a[j]) : v[j];
            float l2 = r1 ? b[j].z : b[j].x;                       // tree[4i+2] / tree[4i]
            bool r2 = (l2 < v[j]);    v[j] = r2 ? (v[j] - l2) : v[j];
            float l3 = r1 ? (r2 ? c1[j].z : c1[j].x)               // 8i+6 / 8i+4
                          : (r2 ? c0[j].z : c0[j].x);              // 8i+2 / 8i
            bool r3 = (l3 < v[j]);    v[j] = r3 ? (v[j] - l3) : v[j];
            idx[j] = 8 * idx[j] + 4 * (int)r1 + 2 * (int)r2 + (int)r3;
        }
    }
    {   // one 2-level round -> level 20
        float a[QPT];
        float4 b[QPT];
#pragma unroll
        for (int j = 0; j < QPT; ++j) {
            int i = idx[j];
            a[j] = __ldg(&g_tree[2 * i]);
            b[j] = __ldg(reinterpret_cast<const float4*>(&g_tree[4 * i]));
        }
#pragma unroll
        for (int j = 0; j < QPT; ++j) {
            bool r1 = (a[j] < v[j]);  v[j] = r1 ? (v[j] - a[j]) : v[j];
            float l2 = r1 ? b[j].z : b[j].x;
            bool r2 = (l2 < v[j]);    v[j] = r2 ? (v[j] - l2) : v[j];
            idx[j] = 4 * idx[j] + 2 * (int)r1 + (int)r2;
        }
    }

    // Leaf bursts for all queries (16 independent LDG.128 in flight; the 4
    // loads of one query share a 64B-aligned region -> 1 cache line each).
    float4 A[QPT], B[QPT], C[QPT], D[QPT];
    int base[QPT];
#pragma unroll
    for (int j = 0; j < QPT; ++j) {
        base[j] = (idx[j] << 4) - BOUND;
        const float4* lp = reinterpret_cast<const float4*>(leaf + base[j]);
        A[j] = __ldg(lp);
        B[j] = __ldg(lp + 1);
        C[j] = __ldg(lp + 2);
        D[j] = __ldg(lp + 3);
    }

#pragma unroll
    for (int j = 0; j < QPT; ++j) {
        float s8_0 = A[j].x + A[j].y, s8_2 = B[j].x + B[j].y;
        float s8_4 = C[j].x + C[j].y, s8_6 = D[j].x + D[j].y;
        float s4_0 = s8_0 + (A[j].z + A[j].w), s4_1 = s8_2 + (B[j].z + B[j].w);
        float s4_2 = s8_4 + (C[j].z + C[j].w);
        float s2_0 = s4_0 + s4_1;
        float vv = v[j];

        bool r1 = (s2_0 < vv); vv = r1 ? (vv - s2_0) : vv;      // level 21
        float l22 = r1 ? s4_2 : s4_0;
        bool r2 = (l22 < vv);  vv = r2 ? (vv - l22) : vv;       // level 22
        float l23 = r1 ? (r2 ? s8_6 : s8_4) : (r2 ? s8_2 : s8_0);
        bool r3 = (l23 < vv);  vv = r3 ? (vv - l23) : vv;       // level 23
        float4 P = r1 ? C[j] : A[j];
        float4 Q = r1 ? D[j] : B[j];
        float4 R = r2 ? Q : P;
        float e0 = r3 ? R.z : R.x;
        float e1 = r3 ? R.w : R.y;
        bool r4 = (e0 < vv);                                    // level 24
        float prio = r4 ? e1 : e0;

        int leafIdx = base[j] + 8 * (int)r1 + 4 * (int)r2 + 2 * (int)r3 + (int)r4;
        int q = qbase + j * 256;
        if (q < batch) {
            out[q] = (float)leafIdx;      // exact in f32 (< 2^24)
            out[batch + q] = prio;
        }
    }
}

extern "C" void kernel_launch(void* const* d_in, const int* in_sizes, int n_in,
                              void* d_out, int out_size) {
    const float* leaf = (const float*)d_in[0];
    const float* frac = (const float*)d_in[1];
    float* out = (float*)d_out;
    const int batch = in_sizes[1];

    build_lower<<<BOUND / 4096, 256>>>(leaf);
    descend<<<(batch + 256 * QPT - 1) / (256 * QPT), 256>>>(leaf, frac, out, batch);
}

// round 7
// speedup vs baseline: 1.0094x; 1.0094x over previous
#include <cuda_runtime.h>
#include <cstdint>

// Internal heap nodes, heap-indexed: g_tree[i] for i in [1, 2^21).
// Levels 0..20 are all materialized (levels 0..11 by the build tail-block).
// Levels 21..23 are recomputed in registers from a 64B leaf burst. All sums
// use the identical left+right pairing as the reference's
// reshape(-1,2).sum(axis=1), so every comparison is bitwise-exact.
#define BOUND (1 << 24)
__device__ float g_tree[1 << 21];          // 8 MB
__device__ unsigned int g_cnt = 0;         // "last block" counter (self-resetting)

// ---------------------------------------------------------------------------
// Build: each block reduces 4096 contiguous leaves; stores levels 20..12.
// The LAST block to finish additionally builds levels 11..0 from level 12
// (threadfence + atomic counter), so descend needs no per-block rebuild.
// ---------------------------------------------------------------------------
__global__ __launch_bounds__(256) void build_lower(const float* __restrict__ leaf) {
    const int b = blockIdx.x;           // 4096 blocks
    const int t = threadIdx.x;
    const int lane = t & 31;
    const int w = t >> 5;               // 8 warps
    __shared__ float s17[32];
    __shared__ float stop[8192];        // heap-indexed scratch for the tail block
    __shared__ bool isLast;

    const float4* __restrict__ in = reinterpret_cast<const float4*>(leaf) + (size_t)b * 1024;

    float* g20 = g_tree + (1u << 20) + (size_t)b * 256;
    float* g19 = g_tree + (1u << 19) + (size_t)b * 128;
    float* g18 = g_tree + (1u << 18) + (size_t)b * 64;
    float* g17 = g_tree + (1u << 17) + (size_t)b * 32;

#pragma unroll
    for (int r = 0; r < 4; ++r) {
        const int q = r * 256 + t;                    // level-22 node id in block
        float4 a = in[q];                             // coalesced LDG.128
        float v = (a.x + a.y) + (a.z + a.w);          // level-22 value (exact pairing)
        float u;
        u = __shfl_down_sync(0xffffffffu, v, 1);  v += u;   // level 21 (not stored)
        u = __shfl_down_sync(0xffffffffu, v, 2);  v += u;   // level 20
        if (!(lane & 3))  g20[r * 64 + w * 8 + (lane >> 2)] = v;
        u = __shfl_down_sync(0xffffffffu, v, 4);  v += u;   // level 19
        if (!(lane & 7))  g19[r * 32 + w * 4 + (lane >> 3)] = v;
        u = __shfl_down_sync(0xffffffffu, v, 8);  v += u;   // level 18
        if (!(lane & 15)) g18[r * 16 + w * 2 + (lane >> 4)] = v;
        u = __shfl_down_sync(0xffffffffu, v, 16); v += u;   // level 17
        if (lane == 0) { g17[r * 8 + w] = v; s17[r * 8 + w] = v; }
    }
    __syncthreads();

    if (w == 0) {
        float v = s17[lane];
        float u;
        float* g16 = g_tree + (1u << 16) + (size_t)b * 16;
        float* g15 = g_tree + (1u << 15) + (size_t)b * 8;
        float* g14 = g_tree + (1u << 14) + (size_t)b * 4;
        float* g13 = g_tree + (1u << 13) + (size_t)b * 2;
        float* g12 = g_tree + (1u << 12) + (size_t)b;
        u = __shfl_down_sync(0xffffffffu, v, 1);  v += u;
        if (!(lane & 1))  g16[lane >> 1] = v;
        u = __shfl_down_sync(0xffffffffu, v, 2);  v += u;
        if (!(lane & 3))  g15[lane >> 2] = v;
        u = __shfl_down_sync(0xffffffffu, v, 4);  v += u;
        if (!(lane & 7))  g14[lane >> 3] = v;
        u = __shfl_down_sync(0xffffffffu, v, 8);  v += u;
        if (!(lane & 15)) g13[lane >> 4] = v;
        u = __shfl_down_sync(0xffffffffu, v, 16); v += u;
        if (lane == 0)    g12[0] = v;
    }
    __syncthreads();

    // ---- tail: last block builds levels 11..0 into g_tree[1..4096) ----
    __threadfence();
    if (t == 0) isLast = (atomicAdd(&g_cnt, 1u) == gridDim.x - 1u);
    __syncthreads();
    if (!isLast) return;

    // Load level 12 (heap [4096, 8192)) into smem heap slots.
    {
        float4* s4p = reinterpret_cast<float4*>(stop);
        const float4* g4 = reinterpret_cast<const float4*>(g_tree);
        for (int i = t; i < 1024; i += 256) s4p[1024 + i] = g4[1024 + i];
    }
    __syncthreads();
#pragma unroll
    for (int n = 2048; n >= 1; n >>= 1) {
        for (int i = t; i < n; i += 256) {
            float v = stop[2 * (n + i)] + stop[2 * (n + i) + 1];
            stop[n + i] = v;
            g_tree[n + i] = v;
        }
        __syncthreads();
    }
    if (t == 0) g_cnt = 0;   // reset for next graph replay
}

// ---------------------------------------------------------------------------
// Descend: no shared memory, no barriers. Levels 1..12 read from g_tree
// (32 KB region -> L1-resident after warmup), 2 levels/round with one scalar
// + one float4 speculative load. Levels 13..20 in (3,3,2)-level rounds with
// vectorized speculative loads. Levels 21..24 + priority from one 64B leaf
// burst. 512 blocks x 128 threads: every SM/L1tex engaged.
// ---------------------------------------------------------------------------
__global__ __launch_bounds__(128) void descend(const float* __restrict__ leaf,
                                               const float* __restrict__ frac,
                                               float* __restrict__ out,
                                               int batch) {
    const int q = blockIdx.x * 128 + threadIdx.x;
    if (q >= batch) return;

    float v = frac[q] * __ldg(&g_tree[1]);
    int idx = 1;

    // Levels 1..12: six 2-level rounds (L1-hit region).
#pragma unroll
    for (int d = 0; d < 6; ++d) {
        float a = __ldg(&g_tree[2 * idx]);
        float4 bb = __ldg(reinterpret_cast<const float4*>(&g_tree[4 * idx]));
        bool r1 = (a < v);   v = r1 ? (v - a) : v;
        float l2 = r1 ? bb.z : bb.x;          // tree[4i+2] / tree[4i]
        bool r2 = (l2 < v);  v = r2 ? (v - l2) : v;
        idx = 4 * idx + 2 * (int)r1 + (int)r2;
    }

    // Levels 13..20: two 3-level rounds, one 2-level round.
#pragma unroll
    for (int round = 0; round < 2; ++round) {
        float a = __ldg(&g_tree[2 * idx]);
        float4 bb = __ldg(reinterpret_cast<const float4*>(&g_tree[4 * idx]));
        float4 c0 = __ldg(reinterpret_cast<const float4*>(&g_tree[8 * idx]));
        float4 c1 = __ldg(reinterpret_cast<const float4*>(&g_tree[8 * idx + 4]));
        bool r1 = (a < v);   v = r1 ? (v - a) : v;
        float l2 = r1 ? bb.z : bb.x;
        bool r2 = (l2 < v);  v = r2 ? (v - l2) : v;
        float l3 = r1 ? (r2 ? c1.z : c1.x) : (r2 ? c0.z : c0.x);
        bool r3 = (l3 < v);  v = r3 ? (v - l3) : v;
        idx = 8 * idx + 4 * (int)r1 + 2 * (int)r2 + (int)r3;
    }
    {
        float a = __ldg(&g_tree[2 * idx]);
        float4 bb = __ldg(reinterpret_cast<const float4*>(&g_tree[4 * idx]));
        bool r1 = (a < v);   v = r1 ? (v - a) : v;
        float l2 = r1 ? bb.z : bb.x;
        bool r2 = (l2 < v);  v = r2 ? (v - l2) : v;
        idx = 4 * idx + 2 * (int)r1 + (int)r2;
    }

    // idx at level 20. Burst the 16 leaves under it (64B aligned, 1 line).
    const int base = (idx << 4) - BOUND;
    const float4* lp = reinterpret_cast<const float4*>(leaf + base);
    float4 A = __ldg(lp);
    float4 B = __ldg(lp + 1);
    float4 C = __ldg(lp + 2);
    float4 D = __ldg(lp + 3);

    float s8_0 = A.x + A.y, s8_2 = B.x + B.y;
    float s8_4 = C.x + C.y, s8_6 = D.x + D.y;
    float s4_0 = s8_0 + (A.z + A.w), s4_1 = s8_2 + (B.z + B.w);
    float s4_2 = s8_4 + (C.z + C.w);
    float s2_0 = s4_0 + s4_1;

    bool r1 = (s2_0 < v); v = r1 ? (v - s2_0) : v;          // level 21
    float l22 = r1 ? s4_2 : s4_0;
    bool r2 = (l22 < v);  v = r2 ? (v - l22) : v;           // level 22
    float l23 = r1 ? (r2 ? s8_6 : s8_4) : (r2 ? s8_2 : s8_0);
    bool r3 = (l23 < v);  v = r3 ? (v - l23) : v;           // level 23
    float4 P = r1 ? C : A;
    float4 Q = r1 ? D : B;
    float4 R = r2 ? Q : P;
    float e0 = r3 ? R.z : R.x;
    float e1 = r3 ? R.w : R.y;
    bool r4 = (e0 < v);                                     // level 24
    float prio = r4 ? e1 : e0;

    const int leafIdx = base + 8 * (int)r1 + 4 * (int)r2 + 2 * (int)r3 + (int)r4;
    out[q] = (float)leafIdx;      // exact in f32 (< 2^24)
    out[batch + q] = prio;
}

extern "C" void kernel_launch(void* const* d_in, const int* in_sizes, int n_in,
                              void* d_out, int out_size) {
    const float* leaf = (const float*)d_in[0];
    const float* frac = (const float*)d_in[1];
    float* out = (float*)d_out;
    const int batch = in_sizes[1];

    build_lower<<<BOUND / 4096, 256>>>(leaf);
    descend<<<(batch + 127) / 128, 128>>>(leaf, frac, out, batch);
}